// round 16
// baseline (speedup 1.0000x reference)
#include <cuda_runtime.h>
#include <cstdint>

// Distral multi-head tiny MLP (N = 32769 heads). Final model (R9-R15):
//   - L2 persists across graph replays; evict_last retention caps at C~52-55MB
//     regardless of tagged-set size (hits ~= C for any protected set >= C).
//   - Best config: protect W1+b1 (52.4MB ~= C) evict_last, stream W2
//     evict_first -> steady DRAM ~68MB, 16.9us (R9).
//   - All structural deviations (smem, TMA, 2-head, reg squeeze, prefetch)
//     regress. R16 = R9 + load-balance fix: 6560 warps -> 4.996 heads/warp
//     (99.5% last-wave utilization vs 61% at R9's 7104 warps), plus
//     __launch_bounds__(256,6) to pin the 6-block/SM residency.

#define HID 100
#define OUT 5

__device__ __forceinline__ uint64_t pol_keep() {
    uint64_t p;
    asm("createpolicy.fractional.L2::evict_last.b64 %0, 1.0;" : "=l"(p));
    return p;
}
__device__ __forceinline__ uint64_t pol_stream() {
    uint64_t p;
    asm("createpolicy.fractional.L2::evict_first.b64 %0, 1.0;" : "=l"(p));
    return p;
}
__device__ __forceinline__ float4 ldg_hint(const float4* p, uint64_t pol) {
    float4 v;
    asm volatile("ld.global.nc.L2::cache_hint.v4.f32 {%0,%1,%2,%3}, [%4], %5;"
                 : "=f"(v.x), "=f"(v.y), "=f"(v.z), "=f"(v.w)
                 : "l"(p), "l"(pol));
    return v;
}

__global__ __launch_bounds__(256, 6) void distral_kernel(
    const float* __restrict__ x,
    const float* __restrict__ W1,
    const float* __restrict__ b1,
    const float* __restrict__ W2,
    const float* __restrict__ b2,
    float* __restrict__ out,
    int n_heads)
{
    const int lane  = threadIdx.x & 31;
    const int gwarp = (blockIdx.x * blockDim.x + threadIdx.x) >> 5;
    const int nwarp = (gridDim.x * blockDim.x) >> 5;

    const uint64_t pk = pol_keep();    // W1,b1: resident set (52.4MB ~= cap)
    const uint64_t ps = pol_stream();  // W2: streaming

    // lane l (l<25) owns hidden units j in [4l, 4l+4)
    for (int head = gwarp; head < n_heads; head += nwarp) {
        const float4* g1 = (const float4*)(W1 + (size_t)head * (HID * 3));
        const float4* gb = (const float4*)(b1 + (size_t)head * HID);
        const float4* g2 = (const float4*)(W2 + (size_t)head * (OUT * HID));

        // batched load burst: all 9 wide loads issued before any compute
        float4 w1a, w1b, w1c, b1v, w2v[OUT];
        if (lane < 25) {
            w1a = ldg_hint(g1 + 3 * lane + 0, pk);
            w1b = ldg_hint(g1 + 3 * lane + 1, pk);
            w1c = ldg_hint(g1 + 3 * lane + 2, pk);
            b1v = ldg_hint(gb + lane, pk);
            #pragma unroll
            for (int o = 0; o < OUT; o++) w2v[o] = ldg_hint(g2 + 25 * o + lane, ps);
        } else {
            w1a = w1b = w1c = b1v = make_float4(0.f, 0.f, 0.f, 0.f);
            #pragma unroll
            for (int o = 0; o < OUT; o++) w2v[o] = make_float4(0.f, 0.f, 0.f, 0.f);
        }

        const float x0 = __ldg(x + (size_t)head * 3 + 0);
        const float x1 = __ldg(x + (size_t)head * 3 + 1);
        const float x2 = __ldg(x + (size_t)head * 3 + 2);

        const float f[12] = { w1a.x, w1a.y, w1a.z, w1a.w,
                              w1b.x, w1b.y, w1b.z, w1b.w,
                              w1c.x, w1c.y, w1c.z, w1c.w };
        const float bb[4] = { b1v.x, b1v.y, b1v.z, b1v.w };

        float h[4];
        #pragma unroll
        for (int k = 0; k < 4; k++) {
            float v = fmaf(f[3 * k + 0], x0,
                      fmaf(f[3 * k + 1], x1,
                      fmaf(f[3 * k + 2], x2, bb[k])));
            h[k] = fmaxf(v, 0.0f);
        }

        float logits[OUT];
        #pragma unroll
        for (int o = 0; o < OUT; o++) {
            float4 q = w2v[o];
            float p = fmaf(q.x, h[0], fmaf(q.y, h[1], fmaf(q.z, h[2], q.w * h[3])));
            #pragma unroll
            for (int s = 16; s; s >>= 1)
                p += __shfl_xor_sync(0xffffffffu, p, s);
            logits[o] = p + __ldg(b2 + (size_t)head * OUT + o);
        }

        float mx = logits[0];
        #pragma unroll
        for (int o = 1; o < OUT; o++) mx = fmaxf(mx, logits[o]);
        float e[OUT], sum = 0.0f;
        #pragma unroll
        for (int o = 0; o < OUT; o++) { e[o] = __expf(logits[o] - mx); sum += e[o]; }
        float inv = __frcp_rn(sum);

        if (lane < OUT)
            out[(size_t)head * OUT + lane] = e[lane] * inv;
    }
}

extern "C" void kernel_launch(void* const* d_in, const int* in_sizes, int n_in,
                              void* d_out, int out_size)
{
    const float* x  = (const float*)d_in[0];
    const float* W1 = (const float*)d_in[1];
    const float* b1 = (const float*)d_in[2];
    const float* W2 = (const float*)d_in[3];
    const float* b2 = (const float*)d_in[4];
    float* out = (float*)d_out;

    const int n_heads = in_sizes[0] / 3;   // x is (N, 3)

    // Load balance: target ~5 heads/warp exactly.
    // warps = ceil(n_heads/5); blocks = ceil(warps/8)  -> 820 for N=32769
    const int warps  = (n_heads + 4) / 5;
    const int blocks = (warps + 7) / 8;

    distral_kernel<<<blocks, 256>>>(x, W1, b1, W2, b2, out, n_heads);
}

// round 17
// speedup vs baseline: 1.1072x; 1.1072x over previous
#include <cuda_runtime.h>
#include <cstdint>

// Distral multi-head tiny MLP (N = 32769 heads). Final model (R9-R16):
//   - L2 persists across graph replays; deterministic evict_last retention
//     caps at C ~52-55MB: protect W1+b1 (52.4MB), stream W2 (evict_first).
//   - Steady DRAM ~68MB; R9 = 16.9us. All structural deviations regress.
//   - Grid MUST be an exact multiple of the per-SM residency (R16 lesson).
// R17 = R9 body, topology 128thr x 12 blocks/SM (1776 blocks = 148*12,
// 7104 warps, 48 warps/SM vs R9's 45, single co-resident wave).

#define HID 100
#define OUT 5

__device__ __forceinline__ uint64_t pol_keep() {
    uint64_t p;
    asm("createpolicy.fractional.L2::evict_last.b64 %0, 1.0;" : "=l"(p));
    return p;
}
__device__ __forceinline__ uint64_t pol_stream() {
    uint64_t p;
    asm("createpolicy.fractional.L2::evict_first.b64 %0, 1.0;" : "=l"(p));
    return p;
}
__device__ __forceinline__ float4 ldg_hint(const float4* p, uint64_t pol) {
    float4 v;
    asm volatile("ld.global.nc.L2::cache_hint.v4.f32 {%0,%1,%2,%3}, [%4], %5;"
                 : "=f"(v.x), "=f"(v.y), "=f"(v.z), "=f"(v.w)
                 : "l"(p), "l"(pol));
    return v;
}

__global__ __launch_bounds__(128, 12) void distral_kernel(
    const float* __restrict__ x,
    const float* __restrict__ W1,
    const float* __restrict__ b1,
    const float* __restrict__ W2,
    const float* __restrict__ b2,
    float* __restrict__ out,
    int n_heads)
{
    const int lane  = threadIdx.x & 31;
    const int gwarp = (blockIdx.x * blockDim.x + threadIdx.x) >> 5;
    const int nwarp = (gridDim.x * blockDim.x) >> 5;

    const uint64_t pk = pol_keep();    // W1,b1: resident set (52.4MB ~= cap)
    const uint64_t ps = pol_stream();  // W2: streaming

    // lane l (l<25) owns hidden units j in [4l, 4l+4)
    for (int head = gwarp; head < n_heads; head += nwarp) {
        const float4* g1 = (const float4*)(W1 + (size_t)head * (HID * 3));
        const float4* gb = (const float4*)(b1 + (size_t)head * HID);
        const float4* g2 = (const float4*)(W2 + (size_t)head * (OUT * HID));

        // batched load burst: all 9 wide loads issued before any compute
        float4 w1a, w1b, w1c, b1v, w2v[OUT];
        if (lane < 25) {
            w1a = ldg_hint(g1 + 3 * lane + 0, pk);
            w1b = ldg_hint(g1 + 3 * lane + 1, pk);
            w1c = ldg_hint(g1 + 3 * lane + 2, pk);
            b1v = ldg_hint(gb + lane, pk);
            #pragma unroll
            for (int o = 0; o < OUT; o++) w2v[o] = ldg_hint(g2 + 25 * o + lane, ps);
        } else {
            w1a = w1b = w1c = b1v = make_float4(0.f, 0.f, 0.f, 0.f);
            #pragma unroll
            for (int o = 0; o < OUT; o++) w2v[o] = make_float4(0.f, 0.f, 0.f, 0.f);
        }

        const float x0 = __ldg(x + (size_t)head * 3 + 0);
        const float x1 = __ldg(x + (size_t)head * 3 + 1);
        const float x2 = __ldg(x + (size_t)head * 3 + 2);

        const float f[12] = { w1a.x, w1a.y, w1a.z, w1a.w,
                              w1b.x, w1b.y, w1b.z, w1b.w,
                              w1c.x, w1c.y, w1c.z, w1c.w };
        const float bb[4] = { b1v.x, b1v.y, b1v.z, b1v.w };

        float h[4];
        #pragma unroll
        for (int k = 0; k < 4; k++) {
            float v = fmaf(f[3 * k + 0], x0,
                      fmaf(f[3 * k + 1], x1,
                      fmaf(f[3 * k + 2], x2, bb[k])));
            h[k] = fmaxf(v, 0.0f);
        }

        float logits[OUT];
        #pragma unroll
        for (int o = 0; o < OUT; o++) {
            float4 q = w2v[o];
            float p = fmaf(q.x, h[0], fmaf(q.y, h[1], fmaf(q.z, h[2], q.w * h[3])));
            #pragma unroll
            for (int s = 16; s; s >>= 1)
                p += __shfl_xor_sync(0xffffffffu, p, s);
            logits[o] = p + __ldg(b2 + (size_t)head * OUT + o);
        }

        float mx = logits[0];
        #pragma unroll
        for (int o = 1; o < OUT; o++) mx = fmaxf(mx, logits[o]);
        float e[OUT], sum = 0.0f;
        #pragma unroll
        for (int o = 0; o < OUT; o++) { e[o] = __expf(logits[o] - mx); sum += e[o]; }
        float inv = __frcp_rn(sum);

        if (lane < OUT)
            out[(size_t)head * OUT + lane] = e[lane] * inv;
    }
}

extern "C" void kernel_launch(void* const* d_in, const int* in_sizes, int n_in,
                              void* d_out, int out_size)
{
    const float* x  = (const float*)d_in[0];
    const float* W1 = (const float*)d_in[1];
    const float* b1 = (const float*)d_in[2];
    const float* W2 = (const float*)d_in[3];
    const float* b2 = (const float*)d_in[4];
    float* out = (float*)d_out;

    const int n_heads = in_sizes[0] / 3;   // x is (N, 3)

    // exact single co-resident wave: 12 blocks/SM * 148 SMs, 128 thr each
    const int blocks = 148 * 12;           // 1776 blocks = 7104 warps
    distral_kernel<<<blocks, 128>>>(x, W1, b1, W2, b2, out, n_heads);
}